// round 1
// baseline (speedup 1.0000x reference)
#include <cuda_runtime.h>
#include <math.h>

// Shapes (fixed by problem)
#define Bn   4
#define Tn   2048
#define Cn   1024
#define Hn   16
#define HSn  64
#define CUTn 1024   // CTX/2^LAYER = 1024, cut = min(T, 1024)

// ---------------- scratch (device globals; no allocation allowed) ----------
__device__ float g_h   [Bn*Tn*Cn];              // LN1 output          (32MB)
__device__ float g_k   [Bn*Hn*Tn*HSn];          // K  [b,h,t,d]        (32MB)
__device__ float g_v   [Bn*Hn*Tn*HSn];          // V  [b,h,t,d]        (32MB)
__device__ float g_q   [Bn*Hn*CUTn*HSn];        // Q  [b,h,s,d]        (16MB)
__device__ float g_att [(size_t)Bn*Hn*CUTn*Tn]; // att [z,s,t]         (512MB)
__device__ float g_o   [Bn*CUTn*Cn];            // head-concat O       (16MB)
__device__ float g_res [Bn*CUTn*Cn];            // residual after proj (16MB)
__device__ float g_h2  [Bn*CUTn*Cn];            // LN2 output          (16MB)
__device__ float g_ff  [Bn*CUTn*4*Cn];          // gelu(lin1) output   (64MB)

// ---------------- LayerNorm: one block per row of C=1024 -------------------
__global__ void __launch_bounds__(256) ln_kernel(const float* __restrict__ x,
                                                 const float* __restrict__ w,
                                                 const float* __restrict__ b,
                                                 float* __restrict__ out)
{
    long row = blockIdx.x;
    int t = threadIdx.x;
    const float4* xr = (const float4*)(x + row * Cn);
    float4 v = xr[t];
    float s  = v.x + v.y + v.z + v.w;
    float s2 = v.x*v.x + v.y*v.y + v.z*v.z + v.w*v.w;
    #pragma unroll
    for (int o = 16; o; o >>= 1) {
        s  += __shfl_xor_sync(0xffffffffu, s,  o);
        s2 += __shfl_xor_sync(0xffffffffu, s2, o);
    }
    __shared__ float rs[8], rs2[8];
    if ((t & 31) == 0) { rs[t >> 5] = s; rs2[t >> 5] = s2; }
    __syncthreads();
    float a = 0.f, c = 0.f;
    #pragma unroll
    for (int i = 0; i < 8; i++) { a += rs[i]; c += rs2[i]; }
    float mean = a * (1.0f / Cn);
    float var  = c * (1.0f / Cn) - mean * mean;
    float inv  = rsqrtf(var + 1e-5f);
    float4 wv = ((const float4*)w)[t];
    float4 bv = ((const float4*)b)[t];
    float4 o4;
    o4.x = (v.x - mean) * inv * wv.x + bv.x;
    o4.y = (v.y - mean) * inv * wv.y + bv.y;
    o4.z = (v.z - mean) * inv * wv.z + bv.z;
    o4.w = (v.w - mean) * inv * wv.w + bv.w;
    ((float4*)(out + row * Cn))[t] = o4;
}

// ---------------- masked softmax over T=2048 --------------------------------
__global__ void __launch_bounds__(256) softmax_kernel(float* __restrict__ att)
{
    long row = blockIdx.x;              // z*CUT + s, z in [0,64)
    int  s   = (int)(row & (CUTn - 1));
    float* p = att + row * (long)Tn;
    int valid = (Tn - CUTn) + s + 1;    // positions 0..(1024+s) inclusive
    int t = threadIdx.x;
    const float scale = 0.03125f;       // C^-0.5 = 1024^-0.5
    float vals[8];
    float mx = -1e30f;
    #pragma unroll
    for (int i = 0; i < 8; i++) {
        int j = t + i * 256;
        float v = p[j] * scale;
        vals[i] = v;
        if (j < valid) mx = fmaxf(mx, v);
    }
    __shared__ float sm[8], sm2[8];
    #pragma unroll
    for (int o = 16; o; o >>= 1) mx = fmaxf(mx, __shfl_xor_sync(0xffffffffu, mx, o));
    if ((t & 31) == 0) sm[t >> 5] = mx;
    __syncthreads();
    #pragma unroll
    for (int i = 0; i < 8; i++) mx = fmaxf(mx, sm[i]);
    float sum = 0.f;
    #pragma unroll
    for (int i = 0; i < 8; i++) {
        int j = t + i * 256;
        if (j < valid) { float e = __expf(vals[i] - mx); vals[i] = e; sum += e; }
        else vals[i] = 0.f;
    }
    #pragma unroll
    for (int o = 16; o; o >>= 1) sum += __shfl_xor_sync(0xffffffffu, sum, o);
    if ((t & 31) == 0) sm2[t >> 5] = sum;
    __syncthreads();
    float total = 0.f;
    #pragma unroll
    for (int i = 0; i < 8; i++) total += sm2[i];
    float invs = 1.0f / total;
    #pragma unroll
    for (int i = 0; i < 8; i++) p[t + i * 256] = vals[i] * invs;
}

// ---------------- generic tiled SGEMM, 64x64 tile, 16-k step ----------------
// MODE:
//  0 MKV  : h[8192,1024] x Wk/Wv([H,C,HS])  -> [b,h,t,d], +bias[H*HS]
//  1 MQ   : h(last cut rows) x Wq           -> [b,h,s,d], +bias
//  2 MQK  : batched z: q[1024,64] x K^T[64,2048] -> att[z]
//  3 MAV  : batched z: att[1024,2048] x V[2048,64] -> o concat [b,s,h*64+d]
//  4 MPROJ: o[4096,1024] x proj_w[1024,1024] + proj_b + x_tail -> res
//  5 MLIN1: h2[4096,1024] x lin1_w[1024,4096] + b, GELU -> ff
//  6 MLIN2: ff[4096,4096] x lin2_w[4096,1024] + b + res -> d_out
#define MKV   0
#define MQ    1
#define MQK   2
#define MAV   3
#define MPROJ 4
#define MLIN1 5
#define MLIN2 6

template<int MODE>
__global__ void __launch_bounds__(256) gemm_kernel(
    const float* __restrict__ A, const float* __restrict__ Bm,
    const float* __restrict__ bias, const float* __restrict__ extra,
    float* __restrict__ out)
{
    constexpr int KD  = (MODE==MQK) ? 64 : (MODE==MAV) ? 2048 : (MODE==MLIN2) ? 4096 : 1024;
    constexpr int LDA = (MODE==MQK) ? 64 : (MODE==MAV) ? 2048 : (MODE==MLIN2) ? 4096 : 1024;
    constexpr int LDB = (MODE==MAV) ? 64 : (MODE==MLIN1) ? 4096 : 1024;

    __shared__ float As[16][68];
    __shared__ float Bs[16][68];

    int bn = blockIdx.x, bm = blockIdx.y, z = blockIdx.z;
    if (MODE == MQK) { A += (long)z * (CUTn*HSn); Bm += (long)z * (Tn*HSn); out += (long)z * ((long)CUTn*Tn); }
    if (MODE == MAV) { A += (long)z * ((long)CUTn*Tn); Bm += (long)z * (Tn*HSn); }

    int tid = threadIdx.x;
    int tx = tid & 15, ty = tid >> 4;
    float acc[4][4] = {};

    for (int k0 = 0; k0 < KD; k0 += 16) {
        // ---- load A tile 64x16 (transposed into smem) ----
        {
            int r = tid >> 2, cq = (tid & 3) * 4;
            int arow = bm * 64 + r;
            long aoff;
            if (MODE == MQ)
                aoff = ((long)(arow >> 10) * Tn + (Tn - CUTn) + (arow & 1023)) * (long)Cn + k0 + cq;
            else
                aoff = (long)arow * LDA + k0 + cq;
            float4 a4 = *(const float4*)(A + aoff);
            As[cq+0][r] = a4.x; As[cq+1][r] = a4.y; As[cq+2][r] = a4.z; As[cq+3][r] = a4.w;
        }
        // ---- load B tile 16x64 ----
        if (MODE == MQK) {
            // Bs[k][j] = K[(bn*64+j)*64 + k0 + k]   (transposed load)
            int j = tid >> 2, kk = (tid & 3) * 4;
            float4 b4 = *(const float4*)(Bm + (long)(bn * 64 + j) * 64 + k0 + kk);
            Bs[kk+0][j] = b4.x; Bs[kk+1][j] = b4.y; Bs[kk+2][j] = b4.z; Bs[kk+3][j] = b4.w;
        } else if (MODE == MKV || MODE == MQ) {
            // W[H,C,HS]: 64-wide n-tile == one head; row-major ldb=64 at head base
            int rb = tid >> 4, cb = (tid & 15) * 4;
            float4 b4 = *(const float4*)(Bm + (long)bn * (Cn*HSn) + (long)(k0 + rb) * 64 + cb);
            *(float4*)&Bs[rb][cb] = b4;
        } else {
            int rb = tid >> 4, cb = (tid & 15) * 4;
            float4 b4 = *(const float4*)(Bm + (long)(k0 + rb) * LDB + bn * 64 + cb);
            *(float4*)&Bs[rb][cb] = b4;
        }
        __syncthreads();
        #pragma unroll
        for (int k = 0; k < 16; k++) {
            float4 a = *(const float4*)&As[k][ty * 4];
            float4 b = *(const float4*)&Bs[k][tx * 4];
            acc[0][0] += a.x*b.x; acc[0][1] += a.x*b.y; acc[0][2] += a.x*b.z; acc[0][3] += a.x*b.w;
            acc[1][0] += a.y*b.x; acc[1][1] += a.y*b.y; acc[1][2] += a.y*b.z; acc[1][3] += a.y*b.w;
            acc[2][0] += a.z*b.x; acc[2][1] += a.z*b.y; acc[2][2] += a.z*b.z; acc[2][3] += a.z*b.w;
            acc[3][0] += a.w*b.x; acc[3][1] += a.w*b.y; acc[3][2] += a.w*b.z; acc[3][3] += a.w*b.w;
        }
        __syncthreads();
    }

    // ---- epilogue ----
    #pragma unroll
    for (int i = 0; i < 4; i++) {
        int m = bm * 64 + ty * 4 + i;
        #pragma unroll
        for (int jj = 0; jj < 4; jj++) {
            int n = bn * 64 + tx * 4 + jj;
            float v = acc[i][jj];
            if (MODE == MKV) {
                v += bias[n];
                int b = m >> 11, t = m & 2047, hh = n >> 6, d = n & 63;
                out[(((long)(b*Hn + hh)) * Tn + t) * HSn + d] = v;
            } else if (MODE == MQ) {
                v += bias[n];
                int b = m >> 10, s = m & 1023, hh = n >> 6, d = n & 63;
                out[(((long)(b*Hn + hh)) * CUTn + s) * HSn + d] = v;
            } else if (MODE == MQK) {
                out[(long)m * Tn + n] = v;
            } else if (MODE == MAV) {
                int b = z >> 4, hh = z & 15;
                out[((long)b * CUTn + m) * Cn + hh * HSn + n] = v;
            } else if (MODE == MPROJ) {
                int b = m >> 10, s = m & 1023;
                v += bias[n] + extra[((long)b * Tn + (Tn - CUTn) + s) * Cn + n];
                out[(long)m * Cn + n] = v;
            } else if (MODE == MLIN1) {
                v += bias[n];
                v = 0.5f * v * (1.0f + erff(v * 0.70710678118654752f));  // exact GELU
                out[(long)m * (4*Cn) + n] = v;
            } else { // MLIN2
                v += bias[n] + extra[(long)m * Cn + n];
                out[(long)m * Cn + n] = v;
            }
        }
    }
}

// ---------------- host launcher --------------------------------------------
extern "C" void kernel_launch(void* const* d_in, const int* in_sizes, int n_in,
                              void* d_out, int out_size)
{
    (void)in_sizes; (void)n_in; (void)out_size;
    const float* x      = (const float*)d_in[0];
    const float* ln1_w  = (const float*)d_in[1];
    const float* ln1_b  = (const float*)d_in[2];
    const float* Wq     = (const float*)d_in[3];
    const float* bq     = (const float*)d_in[4];
    const float* Wk     = (const float*)d_in[5];
    const float* bk     = (const float*)d_in[6];
    const float* Wv     = (const float*)d_in[7];
    const float* bv     = (const float*)d_in[8];
    const float* proj_w = (const float*)d_in[9];
    const float* proj_b = (const float*)d_in[10];
    const float* ln2_w  = (const float*)d_in[11];
    const float* ln2_b  = (const float*)d_in[12];
    const float* lin1_w = (const float*)d_in[13];
    const float* lin1_b = (const float*)d_in[14];
    const float* lin2_w = (const float*)d_in[15];
    const float* lin2_b = (const float*)d_in[16];
    float* out = (float*)d_out;

    float *p_h, *p_k, *p_v, *p_q, *p_att, *p_o, *p_res, *p_h2, *p_ff;
    cudaGetSymbolAddress((void**)&p_h,   g_h);
    cudaGetSymbolAddress((void**)&p_k,   g_k);
    cudaGetSymbolAddress((void**)&p_v,   g_v);
    cudaGetSymbolAddress((void**)&p_q,   g_q);
    cudaGetSymbolAddress((void**)&p_att, g_att);
    cudaGetSymbolAddress((void**)&p_o,   g_o);
    cudaGetSymbolAddress((void**)&p_res, g_res);
    cudaGetSymbolAddress((void**)&p_h2,  g_h2);
    cudaGetSymbolAddress((void**)&p_ff,  g_ff);

    // 1) LN1 over all B*T rows
    ln_kernel<<<Bn*Tn, 256>>>(x, ln1_w, ln1_b, p_h);

    // 2) K, V projections (M=8192, N=1024)
    gemm_kernel<MKV><<<dim3(16,128), 256>>>(p_h, Wk, bk, nullptr, p_k);
    gemm_kernel<MKV><<<dim3(16,128), 256>>>(p_h, Wv, bv, nullptr, p_v);

    // 3) Q projection (M=4096 over last cut rows)
    gemm_kernel<MQ><<<dim3(16,64), 256>>>(p_h, Wq, bq, nullptr, p_q);

    // 4) att = q @ k^T  (batched over z = b*H+h, M=1024, N=2048, K=64)
    gemm_kernel<MQK><<<dim3(32,16,64), 256>>>(p_q, p_k, nullptr, nullptr, p_att);

    // 5) masked softmax (scale 1/32, rectangular causal)
    softmax_kernel<<<Bn*Hn*CUTn, 256>>>(p_att);

    // 6) o = att @ v (batched, M=1024, N=64, K=2048), scattered to head concat
    gemm_kernel<MAV><<<dim3(1,16,64), 256>>>(p_att, p_v, nullptr, nullptr, p_o);

    // 7) res = x_tail + o @ proj_w + proj_b  (M=4096, N=1024)
    gemm_kernel<MPROJ><<<dim3(16,64), 256>>>(p_o, proj_w, proj_b, x, p_res);

    // 8) LN2 over res
    ln_kernel<<<Bn*CUTn, 256>>>(p_res, ln2_w, ln2_b, p_h2);

    // 9) ff = gelu(h2 @ lin1_w + lin1_b)  (M=4096, N=4096)
    gemm_kernel<MLIN1><<<dim3(64,64), 256>>>(p_h2, lin1_w, lin1_b, nullptr, p_ff);

    // 10) out = res + ff @ lin2_w + lin2_b  (M=4096, N=1024, K=4096)
    gemm_kernel<MLIN2><<<dim3(16,64), 256>>>(p_ff, lin2_w, lin2_b, p_res, out);
}

// round 2
// speedup vs baseline: 2.8514x; 2.8514x over previous
#include <cuda_runtime.h>
#include <math.h>

// Shapes (fixed by problem)
#define Bn   4
#define Tn   2048
#define Cn   1024
#define Hn   16
#define HSn  64
#define CUTn 1024

// ---------------- scratch ---------------------------------------------------
__device__ float g_h   [Bn*Tn*Cn];
__device__ float g_k   [Bn*Hn*Tn*HSn];
__device__ float g_v   [Bn*Hn*Tn*HSn];
__device__ float g_q   [Bn*Hn*CUTn*HSn];
__device__ float g_att [(size_t)Bn*Hn*CUTn*Tn];
__device__ float g_o   [Bn*CUTn*Cn];
__device__ float g_res [Bn*CUTn*Cn];
__device__ float g_h2  [Bn*CUTn*Cn];
__device__ float g_ff  [Bn*CUTn*4*Cn];
// tf32-rounded weight copies
__device__ float g_wq  [Hn*Cn*HSn];
__device__ float g_wk  [Hn*Cn*HSn];
__device__ float g_wv  [Hn*Cn*HSn];
__device__ float g_wp  [Cn*Cn];
__device__ float g_w1  [Cn*4*Cn];
__device__ float g_w2  [4*Cn*Cn];

__device__ __forceinline__ float rtf32(float x) {
    unsigned u;
    asm("cvt.rna.tf32.f32 %0, %1;" : "=r"(u) : "f"(x));
    return __uint_as_float(u);
}

__device__ __forceinline__ void cpasync16(float* d, const float* s) {
    unsigned u = (unsigned)__cvta_generic_to_shared(d);
    asm volatile("cp.async.cg.shared.global [%0], [%1], 16;" :: "r"(u), "l"(s));
}

// ---------------- weight tf32 rounding prepass ------------------------------
__global__ void __launch_bounds__(256) round_kernel(const float4* __restrict__ in,
                                                    float4* __restrict__ out, int n4)
{
    int i = blockIdx.x * 256 + threadIdx.x;
    if (i < n4) {
        float4 v = in[i];
        v.x = rtf32(v.x); v.y = rtf32(v.y); v.z = rtf32(v.z); v.w = rtf32(v.w);
        out[i] = v;
    }
}

// ---------------- LayerNorm (tf32-rounded output) ---------------------------
__global__ void __launch_bounds__(256) ln_kernel(const float* __restrict__ x,
                                                 const float* __restrict__ w,
                                                 const float* __restrict__ b,
                                                 float* __restrict__ out)
{
    long row = blockIdx.x;
    int t = threadIdx.x;
    const float4* xr = (const float4*)(x + row * Cn);
    float4 v = xr[t];
    float s  = v.x + v.y + v.z + v.w;
    float s2 = v.x*v.x + v.y*v.y + v.z*v.z + v.w*v.w;
    #pragma unroll
    for (int o = 16; o; o >>= 1) {
        s  += __shfl_xor_sync(0xffffffffu, s,  o);
        s2 += __shfl_xor_sync(0xffffffffu, s2, o);
    }
    __shared__ float rs[8], rs2[8];
    if ((t & 31) == 0) { rs[t >> 5] = s; rs2[t >> 5] = s2; }
    __syncthreads();
    float a = 0.f, c = 0.f;
    #pragma unroll
    for (int i = 0; i < 8; i++) { a += rs[i]; c += rs2[i]; }
    float mean = a * (1.0f / Cn);
    float var  = c * (1.0f / Cn) - mean * mean;
    float inv  = rsqrtf(var + 1e-5f);
    float4 wv = ((const float4*)w)[t];
    float4 bv = ((const float4*)b)[t];
    float4 o4;
    o4.x = rtf32((v.x - mean) * inv * wv.x + bv.x);
    o4.y = rtf32((v.y - mean) * inv * wv.y + bv.y);
    o4.z = rtf32((v.z - mean) * inv * wv.z + bv.z);
    o4.w = rtf32((v.w - mean) * inv * wv.w + bv.w);
    ((float4*)(out + row * Cn))[t] = o4;
}

// ---------------- masked softmax (tf32-rounded output) ----------------------
__global__ void __launch_bounds__(256) softmax_kernel(float* __restrict__ att)
{
    long row = blockIdx.x;
    int  s   = (int)(row & (CUTn - 1));
    float* p = att + row * (long)Tn;
    int valid = (Tn - CUTn) + s + 1;
    int t = threadIdx.x;
    const float scale = 0.03125f;
    float vals[8];
    float mx = -1e30f;
    #pragma unroll
    for (int i = 0; i < 8; i++) {
        int j = t + i * 256;
        float v = p[j] * scale;
        vals[i] = v;
        if (j < valid) mx = fmaxf(mx, v);
    }
    __shared__ float sm[8], sm2[8];
    #pragma unroll
    for (int o = 16; o; o >>= 1) mx = fmaxf(mx, __shfl_xor_sync(0xffffffffu, mx, o));
    if ((t & 31) == 0) sm[t >> 5] = mx;
    __syncthreads();
    #pragma unroll
    for (int i = 0; i < 8; i++) mx = fmaxf(mx, sm[i]);
    float sum = 0.f;
    #pragma unroll
    for (int i = 0; i < 8; i++) {
        int j = t + i * 256;
        if (j < valid) { float e = __expf(vals[i] - mx); vals[i] = e; sum += e; }
        else vals[i] = 0.f;
    }
    #pragma unroll
    for (int o = 16; o; o >>= 1) sum += __shfl_xor_sync(0xffffffffu, sum, o);
    if ((t & 31) == 0) sm2[t >> 5] = sum;
    __syncthreads();
    float total = 0.f;
    #pragma unroll
    for (int i = 0; i < 8; i++) total += sm2[i];
    float invs = 1.0f / total;
    #pragma unroll
    for (int i = 0; i < 8; i++) p[t + i * 256] = rtf32(vals[i] * invs);
}

// ---------------- tensor-core tf32 GEMM ------------------------------------
#define MKV   0
#define MQ    1
#define MQK   2
#define MAV   3
#define MPROJ 4
#define MLIN1 5
#define MLIN2 6

template<int MODE, int BM, int BN, int BK, int WM, int WN, bool BKM>
__global__ void __launch_bounds__(256) tc_gemm(
    const float* __restrict__ A, const float* __restrict__ Bm,
    const float* __restrict__ bias, const float* __restrict__ extra,
    float* __restrict__ out)
{
    constexpr int KD  = (MODE==MQK) ? 64 : (MODE==MAV) ? 2048 : (MODE==MLIN2) ? 4096 : 1024;
    constexpr int LDA = (MODE==MQK) ? 64 : (MODE==MAV) ? 2048 : (MODE==MLIN2) ? 4096 : 1024;
    constexpr int LDB = (MODE==MAV) ? 64 : (MODE==MLIN1) ? 4096 : 1024;
    constexpr int ASTR = BK + 4;
    constexpr int BSTR = BKM ? (BK + 4) : (BN + 8);
    constexpr int ASZ  = BM * ASTR;
    constexpr int BSZ  = BKM ? BN * BSTR : BK * BSTR;

    extern __shared__ float smp[];
    float* Asm[2] = { smp, smp + ASZ };
    float* Bsm[2] = { smp + 2*ASZ, smp + 2*ASZ + BSZ };

    int bn = blockIdx.x, bm = blockIdx.y, z = blockIdx.z;
    if (MODE == MQK) { A += (long)z*(CUTn*HSn); Bm += (long)z*(Tn*HSn); out += (long)z*((long)CUTn*Tn); }
    if (MODE == MAV) { A += (long)z*((long)CUTn*Tn); Bm += (long)z*(Tn*HSn); }

    int tid = threadIdx.x;

    auto loadA = [&](float* As, int k0) {
        constexpr int NCH = BM*BK/4/256;
        #pragma unroll
        for (int i = 0; i < NCH; i++) {
            int c = i*256 + tid;
            int m = c >> 3;           // BK/4 == 8
            int kq = (c & 7) * 4;
            long src;
            if (MODE == MQ) {
                int r = bm*BM + m;
                src = ((long)(r >> 10)*Tn + (Tn - CUTn) + (r & 1023))*(long)Cn + k0 + kq;
            } else {
                src = (long)(bm*BM + m)*LDA + k0 + kq;
            }
            cpasync16(As + m*ASTR + kq, A + src);
        }
    };
    auto loadB = [&](float* Bs, int k0) {
        if (BKM) {
            constexpr int NCH = BN*BK/4/256;
            #pragma unroll
            for (int i = 0; i < NCH; i++) {
                int c = i*256 + tid; int n = c >> 3; int kq = (c & 7)*4;
                cpasync16(Bs + n*BSTR + kq, Bm + (long)(bn*BN + n)*64 + k0 + kq);
            }
        } else {
            constexpr int CPR = BN/4;
            constexpr int NCH = BK*BN/4/256;
            #pragma unroll
            for (int i = 0; i < NCH; i++) {
                int c = i*256 + tid; int k = c / CPR; int nq = (c % CPR)*4;
                long src;
                if (MODE == MKV || MODE == MQ) {
                    int n = bn*BN + nq;
                    src = (long)(n >> 6)*(Cn*HSn) + (long)(k0 + k)*HSn + (n & 63);
                } else {
                    src = (long)(k0 + k)*LDB + bn*BN + nq;
                }
                cpasync16(Bs + k*BSTR + nq, Bm + src);
            }
        }
    };

    int lane = tid & 31, g = lane >> 2, tq = lane & 3;
    int wid = tid >> 5;
    constexpr int WNn = BN/WN;
    int wn_i = wid % WNn, wm_i = wid / WNn;
    constexpr int MF = WM/16, NF = WN/8;
    float acc[MF][NF][4];
    #pragma unroll
    for (int a = 0; a < MF; a++)
        #pragma unroll
        for (int b = 0; b < NF; b++)
            #pragma unroll
            for (int i = 0; i < 4; i++) acc[a][b][i] = 0.f;

    const int NIT = KD / BK;
    loadA(Asm[0], 0); loadB(Bsm[0], 0);
    asm volatile("cp.async.commit_group;");

    for (int it = 0; it < NIT; ++it) {
        if (it + 1 < NIT) {
            loadA(Asm[(it+1)&1], (it+1)*BK);
            loadB(Bsm[(it+1)&1], (it+1)*BK);
            asm volatile("cp.async.commit_group;");
            asm volatile("cp.async.wait_group 1;");
        } else {
            asm volatile("cp.async.wait_group 0;");
        }
        __syncthreads();
        const float* As = Asm[it & 1];
        const float* Bs = Bsm[it & 1];
        #pragma unroll
        for (int kf = 0; kf < BK/8; kf++) {
            unsigned af[MF][4]; unsigned bf[NF][2];
            #pragma unroll
            for (int mf = 0; mf < MF; mf++) {
                const float* Ab = As + (wm_i*WM + mf*16)*ASTR + kf*8;
                af[mf][0] = __float_as_uint(Ab[(g    )*ASTR + tq    ]);
                af[mf][1] = __float_as_uint(Ab[(g + 8)*ASTR + tq    ]);
                af[mf][2] = __float_as_uint(Ab[(g    )*ASTR + tq + 4]);
                af[mf][3] = __float_as_uint(Ab[(g + 8)*ASTR + tq + 4]);
            }
            #pragma unroll
            for (int nf = 0; nf < NF; nf++) {
                if (BKM) {
                    const float* Bb = Bs + (wn_i*WN + nf*8 + g)*BSTR + kf*8;
                    bf[nf][0] = __float_as_uint(Bb[tq]);
                    bf[nf][1] = __float_as_uint(Bb[tq + 4]);
                } else {
                    const float* Bb = Bs + (kf*8)*BSTR + wn_i*WN + nf*8 + g;
                    bf[nf][0] = __float_as_uint(Bb[(tq    )*BSTR]);
                    bf[nf][1] = __float_as_uint(Bb[(tq + 4)*BSTR]);
                }
            }
            #pragma unroll
            for (int mf = 0; mf < MF; mf++)
                #pragma unroll
                for (int nf = 0; nf < NF; nf++)
                    asm volatile(
                        "mma.sync.aligned.m16n8k8.row.col.f32.tf32.tf32.f32 "
                        "{%0,%1,%2,%3},{%4,%5,%6,%7},{%8,%9},{%0,%1,%2,%3};"
                        : "+f"(acc[mf][nf][0]), "+f"(acc[mf][nf][1]),
                          "+f"(acc[mf][nf][2]), "+f"(acc[mf][nf][3])
                        : "r"(af[mf][0]), "r"(af[mf][1]), "r"(af[mf][2]), "r"(af[mf][3]),
                          "r"(bf[nf][0]), "r"(bf[nf][1]));
        }
        __syncthreads();
    }

    // epilogue
    #pragma unroll
    for (int mf = 0; mf < MF; mf++)
        #pragma unroll
        for (int nf = 0; nf < NF; nf++)
            #pragma unroll
            for (int i = 0; i < 4; i++) {
                int m = bm*BM + wm_i*WM + mf*16 + g + ((i & 2) ? 8 : 0);
                int n = bn*BN + wn_i*WN + nf*8 + tq*2 + (i & 1);
                float v = acc[mf][nf][i];
                if (MODE == MKV) {
                    v += bias[n]; v = rtf32(v);
                    int b = m >> 11, t = m & 2047, hh = n >> 6, d = n & 63;
                    out[(((long)(b*Hn + hh))*Tn + t)*HSn + d] = v;
                } else if (MODE == MQ) {
                    v += bias[n]; v = rtf32(v);
                    int b = m >> 10, s = m & 1023, hh = n >> 6, d = n & 63;
                    out[(((long)(b*Hn + hh))*CUTn + s)*HSn + d] = v;
                } else if (MODE == MQK) {
                    out[(long)m*Tn + n] = v;
                } else if (MODE == MAV) {
                    int b = z >> 4, hh = z & 15;
                    out[((long)b*CUTn + m)*Cn + hh*HSn + n] = rtf32(v);
                } else if (MODE == MPROJ) {
                    int b = m >> 10, s = m & 1023;
                    v += bias[n] + extra[((long)b*Tn + (Tn - CUTn) + s)*Cn + n];
                    out[(long)m*Cn + n] = v;
                } else if (MODE == MLIN1) {
                    v += bias[n];
                    v = 0.5f * v * (1.0f + erff(v * 0.70710678118654752f));
                    out[(long)m*(4*Cn) + n] = rtf32(v);
                } else { // MLIN2
                    v += bias[n] + extra[(long)m*Cn + n];
                    out[(long)m*Cn + n] = v;
                }
            }
}

// ---------------- host launcher ---------------------------------------------
extern "C" void kernel_launch(void* const* d_in, const int* in_sizes, int n_in,
                              void* d_out, int out_size)
{
    (void)in_sizes; (void)n_in; (void)out_size;
    const float* x      = (const float*)d_in[0];
    const float* ln1_w  = (const float*)d_in[1];
    const float* ln1_b  = (const float*)d_in[2];
    const float* Wq     = (const float*)d_in[3];
    const float* bq     = (const float*)d_in[4];
    const float* Wk     = (const float*)d_in[5];
    const float* bk     = (const float*)d_in[6];
    const float* Wv     = (const float*)d_in[7];
    const float* bv     = (const float*)d_in[8];
    const float* proj_w = (const float*)d_in[9];
    const float* proj_b = (const float*)d_in[10];
    const float* ln2_w  = (const float*)d_in[11];
    const float* ln2_b  = (const float*)d_in[12];
    const float* lin1_w = (const float*)d_in[13];
    const float* lin1_b = (const float*)d_in[14];
    const float* lin2_w = (const float*)d_in[15];
    const float* lin2_b = (const float*)d_in[16];
    float* out = (float*)d_out;

    float *p_h, *p_k, *p_v, *p_q, *p_att, *p_o, *p_res, *p_h2, *p_ff;
    float *p_wq, *p_wk, *p_wv, *p_wp, *p_w1, *p_w2;
    cudaGetSymbolAddress((void**)&p_h,   g_h);
    cudaGetSymbolAddress((void**)&p_k,   g_k);
    cudaGetSymbolAddress((void**)&p_v,   g_v);
    cudaGetSymbolAddress((void**)&p_q,   g_q);
    cudaGetSymbolAddress((void**)&p_att, g_att);
    cudaGetSymbolAddress((void**)&p_o,   g_o);
    cudaGetSymbolAddress((void**)&p_res, g_res);
    cudaGetSymbolAddress((void**)&p_h2,  g_h2);
    cudaGetSymbolAddress((void**)&p_ff,  g_ff);
    cudaGetSymbolAddress((void**)&p_wq,  g_wq);
    cudaGetSymbolAddress((void**)&p_wk,  g_wk);
    cudaGetSymbolAddress((void**)&p_wv,  g_wv);
    cudaGetSymbolAddress((void**)&p_wp,  g_wp);
    cudaGetSymbolAddress((void**)&p_w1,  g_w1);
    cudaGetSymbolAddress((void**)&p_w2,  g_w2);

    // dynamic smem sizes
    const int S_STD = 2*(128*36 + 32*136)*4;   // 71680
    const int S_QK  = 2*(128*36 + 128*36)*4;   // 73728
    const int S_AV  = 2*(128*36 + 32*72)*4;    // 55296
    cudaFuncSetAttribute((const void*)tc_gemm<MKV,  128,128,32,64,32,false>, cudaFuncAttributeMaxDynamicSharedMemorySize, S_STD);
    cudaFuncSetAttribute((const void*)tc_gemm<MQ,   128,128,32,64,32,false>, cudaFuncAttributeMaxDynamicSharedMemorySize, S_STD);
    cudaFuncSetAttribute((const void*)tc_gemm<MQK,  128,128,32,64,32,true >, cudaFuncAttributeMaxDynamicSharedMemorySize, S_QK);
    cudaFuncSetAttribute((const void*)tc_gemm<MAV,  128, 64,32,32,32,false>, cudaFuncAttributeMaxDynamicSharedMemorySize, S_AV);
    cudaFuncSetAttribute((const void*)tc_gemm<MPROJ,128,128,32,64,32,false>, cudaFuncAttributeMaxDynamicSharedMemorySize, S_STD);
    cudaFuncSetAttribute((const void*)tc_gemm<MLIN1,128,128,32,64,32,false>, cudaFuncAttributeMaxDynamicSharedMemorySize, S_STD);
    cudaFuncSetAttribute((const void*)tc_gemm<MLIN2,128,128,32,64,32,false>, cudaFuncAttributeMaxDynamicSharedMemorySize, S_STD);

    // 0) round weights to tf32 (prepass)
    const int WSZ = Hn*Cn*HSn; // 1M elements
    round_kernel<<<WSZ/4/256, 256>>>((const float4*)Wq,     (float4*)p_wq, WSZ/4);
    round_kernel<<<WSZ/4/256, 256>>>((const float4*)Wk,     (float4*)p_wk, WSZ/4);
    round_kernel<<<WSZ/4/256, 256>>>((const float4*)Wv,     (float4*)p_wv, WSZ/4);
    round_kernel<<<(Cn*Cn)/4/256, 256>>>((const float4*)proj_w, (float4*)p_wp, Cn*Cn/4);
    round_kernel<<<(Cn*4*Cn)/4/256, 256>>>((const float4*)lin1_w, (float4*)p_w1, Cn*4*Cn/4);
    round_kernel<<<(4*Cn*Cn)/4/256, 256>>>((const float4*)lin2_w, (float4*)p_w2, 4*Cn*Cn/4);

    // 1) LN1
    ln_kernel<<<Bn*Tn, 256>>>(x, ln1_w, ln1_b, p_h);

    // 2) K, V projections
    tc_gemm<MKV,128,128,32,64,32,false><<<dim3(8,64), 256, S_STD>>>(p_h, p_wk, bk, nullptr, p_k);
    tc_gemm<MKV,128,128,32,64,32,false><<<dim3(8,64), 256, S_STD>>>(p_h, p_wv, bv, nullptr, p_v);

    // 3) Q projection
    tc_gemm<MQ,128,128,32,64,32,false><<<dim3(8,32), 256, S_STD>>>(p_h, p_wq, bq, nullptr, p_q);

    // 4) att = q @ k^T
    tc_gemm<MQK,128,128,32,64,32,true><<<dim3(16,8,64), 256, S_QK>>>(p_q, p_k, nullptr, nullptr, p_att);

    // 5) softmax
    softmax_kernel<<<Bn*Hn*CUTn, 256>>>(p_att);

    // 6) o = att @ v
    tc_gemm<MAV,128,64,32,32,32,false><<<dim3(1,8,64), 256, S_AV>>>(p_att, p_v, nullptr, nullptr, p_o);

    // 7) res = x_tail + o @ proj_w + proj_b
    tc_gemm<MPROJ,128,128,32,64,32,false><<<dim3(8,32), 256, S_STD>>>(p_o, p_wp, proj_b, x, p_res);

    // 8) LN2
    ln_kernel<<<Bn*CUTn, 256>>>(p_res, ln2_w, ln2_b, p_h2);

    // 9) ff = gelu(h2 @ lin1_w + lin1_b)
    tc_gemm<MLIN1,128,128,32,64,32,false><<<dim3(32,32), 256, S_STD>>>(p_h2, p_w1, lin1_b, nullptr, p_ff);

    // 10) out = res + ff @ lin2_w + lin2_b
    tc_gemm<MLIN2,128,128,32,64,32,false><<<dim3(8,32), 256, S_STD>>>(p_ff, p_w2, lin2_b, p_res, out);
}

// round 3
// speedup vs baseline: 3.4228x; 1.2004x over previous
#include <cuda_runtime.h>
#include <math.h>

// Shapes (fixed by problem)
#define Bn   4
#define Tn   2048
#define Cn   1024
#define Hn   16
#define HSn  64
#define CUTn 1024

// ---------------- scratch ---------------------------------------------------
__device__ float g_h   [Bn*Tn*Cn];
__device__ float g_k   [Bn*Hn*Tn*HSn];
__device__ float g_v   [Bn*Hn*Tn*HSn];
__device__ float g_q   [Bn*Hn*CUTn*HSn];
__device__ float g_o   [Bn*CUTn*Cn];
__device__ float g_res [Bn*CUTn*Cn];
__device__ float g_h2  [Bn*CUTn*Cn];
__device__ float g_ff  [Bn*CUTn*4*Cn];
// tf32-rounded weight copies
__device__ float g_wq  [Hn*Cn*HSn];
__device__ float g_wk  [Hn*Cn*HSn];
__device__ float g_wv  [Hn*Cn*HSn];
__device__ float g_wp  [Cn*Cn];
__device__ float g_w1  [Cn*4*Cn];
__device__ float g_w2  [4*Cn*Cn];

__device__ __forceinline__ float rtf32(float x) {
    unsigned u;
    asm("cvt.rna.tf32.f32 %0, %1;" : "=r"(u) : "f"(x));
    return __uint_as_float(u);
}
__device__ __forceinline__ void cpasync16(float* d, const float* s) {
    unsigned u = (unsigned)__cvta_generic_to_shared(d);
    asm volatile("cp.async.cg.shared.global [%0], [%1], 16;" :: "r"(u), "l"(s));
}
__device__ __forceinline__ void mma_tf32(float* c, unsigned a0, unsigned a1,
                                         unsigned a2, unsigned a3,
                                         unsigned b0, unsigned b1) {
    asm volatile(
        "mma.sync.aligned.m16n8k8.row.col.f32.tf32.tf32.f32 "
        "{%0,%1,%2,%3},{%4,%5,%6,%7},{%8,%9},{%0,%1,%2,%3};"
        : "+f"(c[0]), "+f"(c[1]), "+f"(c[2]), "+f"(c[3])
        : "r"(a0), "r"(a1), "r"(a2), "r"(a3), "r"(b0), "r"(b1));
}

// ---------------- merged weight tf32 rounding prepass -----------------------
struct RoundArgs {
    const float4* s[6];
    float4*       d[6];
    int           end[6];   // cumulative float4 counts
};
__global__ void __launch_bounds__(256) round_all(RoundArgs a)
{
    int i = blockIdx.x * 256 + threadIdx.x;
    if (i >= a.end[5]) return;
    int r = 0, base = 0;
    #pragma unroll
    for (int j = 0; j < 5; j++)
        if (i >= a.end[j]) { r = j + 1; base = a.end[j]; }
    float4 v = a.s[r][i - base];
    v.x = rtf32(v.x); v.y = rtf32(v.y); v.z = rtf32(v.z); v.w = rtf32(v.w);
    a.d[r][i - base] = v;
}

// ---------------- LayerNorm (tf32-rounded output) ---------------------------
__global__ void __launch_bounds__(256) ln_kernel(const float* __restrict__ x,
                                                 const float* __restrict__ w,
                                                 const float* __restrict__ b,
                                                 float* __restrict__ out)
{
    long row = blockIdx.x;
    int t = threadIdx.x;
    const float4* xr = (const float4*)(x + row * Cn);
    float4 v = xr[t];
    float s  = v.x + v.y + v.z + v.w;
    float s2 = v.x*v.x + v.y*v.y + v.z*v.z + v.w*v.w;
    #pragma unroll
    for (int o = 16; o; o >>= 1) {
        s  += __shfl_xor_sync(0xffffffffu, s,  o);
        s2 += __shfl_xor_sync(0xffffffffu, s2, o);
    }
    __shared__ float rs[8], rs2[8];
    if ((t & 31) == 0) { rs[t >> 5] = s; rs2[t >> 5] = s2; }
    __syncthreads();
    float a = 0.f, c = 0.f;
    #pragma unroll
    for (int i = 0; i < 8; i++) { a += rs[i]; c += rs2[i]; }
    float mean = a * (1.0f / Cn);
    float var  = c * (1.0f / Cn) - mean * mean;
    float inv  = rsqrtf(var + 1e-5f);
    float4 wv = ((const float4*)w)[t];
    float4 bv = ((const float4*)b)[t];
    float4 o4;
    o4.x = rtf32((v.x - mean) * inv * wv.x + bv.x);
    o4.y = rtf32((v.y - mean) * inv * wv.y + bv.y);
    o4.z = rtf32((v.z - mean) * inv * wv.z + bv.z);
    o4.w = rtf32((v.w - mean) * inv * wv.w + bv.w);
    ((float4*)(out + row * Cn))[t] = o4;
}

// ---------------- fused flash attention -------------------------------------
// Grid: (8 q-tiles, 64 z=b*H+h). Block: 256 thr = 8 warps; warp owns 16 q-rows.
// Key tiles of 64 over T=2048, cp.async double buffered.
#define FQS 68
#define FKS 68
#define FVS 72

__global__ void __launch_bounds__(256) flash_kernel(
    const float* __restrict__ Q, const float* __restrict__ K,
    const float* __restrict__ V, float* __restrict__ O)
{
    int bm = blockIdx.x, z = blockIdx.y;
    const float* Qz = Q + (long)z*(CUTn*HSn) + (long)bm*128*HSn;
    const float* Kz = K + (long)z*(Tn*HSn);
    const float* Vz = V + (long)z*(Tn*HSn);

    extern __shared__ float sm[];
    float* Qs  = sm;                      // [128][FQS]
    float* Ksm = Qs  + 128*FQS;           // [2][64][FKS]
    float* Vsm = Ksm + 2*64*FKS;          // [2][64][FVS]
    float* Ps  = Vsm + 2*64*FVS;          // [128][FQS]

    int tid = threadIdx.x, lane = tid & 31, wid = tid >> 5;
    int g = lane >> 2, tq = lane & 3;

    // load Q tile (group 0 together with K0/V0)
    #pragma unroll
    for (int i = 0; i < 8; i++) {
        int c = i*256 + tid; int r = c >> 4, cq = (c & 15) * 4;
        cpasync16(Qs + r*FQS + cq, Qz + r*64 + cq);
    }
    #pragma unroll
    for (int i = 0; i < 4; i++) {
        int c = i*256 + tid; int r = c >> 4, cq = (c & 15) * 4;
        cpasync16(Ksm + r*FKS + cq, Kz + r*64 + cq);
        cpasync16(Vsm + r*FVS + cq, Vz + r*64 + cq);
    }
    asm volatile("cp.async.commit_group;");

    float m0 = -1e30f, m1 = -1e30f, l0 = 0.f, l1 = 0.f;
    float oacc[8][4];
    #pragma unroll
    for (int j = 0; j < 8; j++) { oacc[j][0]=0.f; oacc[j][1]=0.f; oacc[j][2]=0.f; oacc[j][3]=0.f; }

    const int ktmax  = min(31, 17 + 2*bm);
    const int ktfull = 15 + 2*bm;
    const int sg0    = bm*128 + wid*16 + g;   // global q row (c0/c1); +8 for c2/c3

    for (int kt = 0; kt <= ktmax; kt++) {
        int buf = kt & 1;
        if (kt < ktmax) {
            const float* Kp = Kz + (long)(kt+1)*64*64;
            const float* Vp = Vz + (long)(kt+1)*64*64;
            int b2 = buf ^ 1;
            #pragma unroll
            for (int i = 0; i < 4; i++) {
                int c = i*256 + tid; int r = c >> 4, cq = (c & 15) * 4;
                cpasync16(Ksm + b2*64*FKS + r*FKS + cq, Kp + r*64 + cq);
                cpasync16(Vsm + b2*64*FVS + r*FVS + cq, Vp + r*64 + cq);
            }
            asm volatile("cp.async.commit_group;");
            asm volatile("cp.async.wait_group 1;");
        } else {
            asm volatile("cp.async.wait_group 0;");
        }
        __syncthreads();

        // S = Q.K^T  (q pre-scaled by 2^-5)
        float sacc[8][4];
        #pragma unroll
        for (int j = 0; j < 8; j++) { sacc[j][0]=0.f; sacc[j][1]=0.f; sacc[j][2]=0.f; sacc[j][3]=0.f; }
        const float* Kb = Ksm + buf*64*FKS;
        #pragma unroll
        for (int kf = 0; kf < 8; kf++) {
            const float* Ab = Qs + (wid*16)*FQS + kf*8;
            unsigned a0 = __float_as_uint(Ab[ g     *FQS + tq    ]);
            unsigned a1 = __float_as_uint(Ab[(g + 8)*FQS + tq    ]);
            unsigned a2 = __float_as_uint(Ab[ g     *FQS + tq + 4]);
            unsigned a3 = __float_as_uint(Ab[(g + 8)*FQS + tq + 4]);
            #pragma unroll
            for (int nf = 0; nf < 8; nf++) {
                const float* Bb = Kb + (nf*8 + g)*FKS + kf*8;
                mma_tf32(sacc[nf], a0, a1, a2, a3,
                         __float_as_uint(Bb[tq]), __float_as_uint(Bb[tq + 4]));
            }
        }
        // rectangular causal mask (only partial tiles)
        if (kt > ktfull) {
            #pragma unroll
            for (int nf = 0; nf < 8; nf++)
                #pragma unroll
                for (int i = 0; i < 4; i++) {
                    int jg = kt*64 + nf*8 + tq*2 + (i & 1);
                    int sg = sg0 + ((i & 2) ? 8 : 0);
                    if (jg > 1024 + sg) sacc[nf][i] = -1e30f;
                }
        }
        // online softmax
        float mx0 = -1e30f, mx1 = -1e30f;
        #pragma unroll
        for (int nf = 0; nf < 8; nf++) {
            mx0 = fmaxf(mx0, fmaxf(sacc[nf][0], sacc[nf][1]));
            mx1 = fmaxf(mx1, fmaxf(sacc[nf][2], sacc[nf][3]));
        }
        mx0 = fmaxf(mx0, __shfl_xor_sync(0xffffffffu, mx0, 1));
        mx0 = fmaxf(mx0, __shfl_xor_sync(0xffffffffu, mx0, 2));
        mx1 = fmaxf(mx1, __shfl_xor_sync(0xffffffffu, mx1, 1));
        mx1 = fmaxf(mx1, __shfl_xor_sync(0xffffffffu, mx1, 2));
        float mn0 = fmaxf(m0, mx0), mn1 = fmaxf(m1, mx1);
        float f0 = __expf(m0 - mn0), f1 = __expf(m1 - mn1);
        float s0 = 0.f, s1 = 0.f;
        float* Pw0 = Ps + (wid*16 + g    )*FQS + tq*2;
        float* Pw1 = Ps + (wid*16 + g + 8)*FQS + tq*2;
        #pragma unroll
        for (int nf = 0; nf < 8; nf++) {
            float p0 = __expf(sacc[nf][0] - mn0), p1 = __expf(sacc[nf][1] - mn0);
            float p2 = __expf(sacc[nf][2] - mn1), p3 = __expf(sacc[nf][3] - mn1);
            s0 += p0 + p1; s1 += p2 + p3;
            *(float2*)(Pw0 + nf*8) = make_float2(p0, p1);
            *(float2*)(Pw1 + nf*8) = make_float2(p2, p3);
        }
        s0 += __shfl_xor_sync(0xffffffffu, s0, 1); s0 += __shfl_xor_sync(0xffffffffu, s0, 2);
        s1 += __shfl_xor_sync(0xffffffffu, s1, 1); s1 += __shfl_xor_sync(0xffffffffu, s1, 2);
        l0 = l0*f0 + s0; l1 = l1*f1 + s1; m0 = mn0; m1 = mn1;
        #pragma unroll
        for (int j = 0; j < 8; j++) {
            oacc[j][0] *= f0; oacc[j][1] *= f0; oacc[j][2] *= f1; oacc[j][3] *= f1;
        }
        __syncwarp();   // P stores visible to cross-lane A-frag reads (warp-private rows)

        // O += P.V
        const float* Vb = Vsm + buf*64*FVS;
        #pragma unroll
        for (int kf = 0; kf < 8; kf++) {
            const float* Ab = Ps + (wid*16)*FQS + kf*8;
            unsigned a0 = __float_as_uint(Ab[ g     *FQS + tq    ]);
            unsigned a1 = __float_as_uint(Ab[(g + 8)*FQS + tq    ]);
            unsigned a2 = __float_as_uint(Ab[ g     *FQS + tq + 4]);
            unsigned a3 = __float_as_uint(Ab[(g + 8)*FQS + tq + 4]);
            #pragma unroll
            for (int nf = 0; nf < 8; nf++) {
                const float* Bb = Vb + (kf*8)*FVS + nf*8 + g;
                mma_tf32(oacc[nf], a0, a1, a2, a3,
                         __float_as_uint(Bb[ tq     *FVS]),
                         __float_as_uint(Bb[(tq + 4)*FVS]));
            }
        }
        __syncthreads();
    }

    // epilogue: O /= l, scatter to head-concat layout
    int b = z >> 4, hh = z & 15;
    float il0 = 1.f / l0, il1 = 1.f / l1;
    #pragma unroll
    for (int nf = 0; nf < 8; nf++)
        #pragma unroll
        for (int i = 0; i < 4; i++) {
            int row = wid*16 + g + ((i & 2) ? 8 : 0);
            int s = bm*128 + row;
            int d = nf*8 + tq*2 + (i & 1);
            O[((long)b*CUTn + s)*Cn + hh*64 + d] = rtf32(oacc[nf][i] * ((i & 2) ? il1 : il0));
        }
}

// ---------------- tensor-core tf32 GEMM ------------------------------------
#define MKV   0
#define MQ    1
#define MPROJ 4
#define MLIN1 5
#define MLIN2 6

template<int MODE, int BM, int BN, int BK, int WM, int WN>
__global__ void __launch_bounds__(256) tc_gemm(
    const float* __restrict__ A, const float* __restrict__ Bm,
    const float* __restrict__ bias, const float* __restrict__ extra,
    float* __restrict__ out)
{
    constexpr int KD  = (MODE==MLIN2) ? 4096 : 1024;
    constexpr int LDA = (MODE==MLIN2) ? 4096 : 1024;
    constexpr int LDB = (MODE==MLIN1) ? 4096 : 1024;
    constexpr int ASTR = BK + 4;
    constexpr int BSTR = BN + 8;
    constexpr int ASZ  = BM * ASTR;
    constexpr int BSZ  = BK * BSTR;

    extern __shared__ float smp[];
    float* Asm[2] = { smp, smp + ASZ };
    float* Bsm[2] = { smp + 2*ASZ, smp + 2*ASZ + BSZ };

    int bn = blockIdx.x, bm = blockIdx.y;
    int tid = threadIdx.x;

    auto loadA = [&](float* As, int k0) {
        constexpr int NCH = BM*BK/4/256;
        #pragma unroll
        for (int i = 0; i < NCH; i++) {
            int c = i*256 + tid;
            int m = c >> 3;
            int kq = (c & 7) * 4;
            long src;
            if (MODE == MQ) {
                int r = bm*BM + m;
                src = ((long)(r >> 10)*Tn + (Tn - CUTn) + (r & 1023))*(long)Cn + k0 + kq;
            } else {
                src = (long)(bm*BM + m)*LDA + k0 + kq;
            }
            cpasync16(As + m*ASTR + kq, A + src);
        }
    };
    auto loadB = [&](float* Bs, int k0) {
        constexpr int CPR = BN/4;
        constexpr int NCH = BK*BN/4/256;
        #pragma unroll
        for (int i = 0; i < NCH; i++) {
            int c = i*256 + tid; int k = c / CPR; int nq = (c % CPR)*4;
            long src;
            if (MODE == MKV || MODE == MQ) {
                int n = bn*BN + nq;
                src = (long)(n >> 6)*(Cn*HSn) + (long)(k0 + k)*HSn + (n & 63);
            } else {
                src = (long)(k0 + k)*LDB + bn*BN + nq;
            }
            cpasync16(Bs + k*BSTR + nq, Bm + src);
        }
    };

    int lane = tid & 31, g = lane >> 2, tq = lane & 3;
    int wid = tid >> 5;
    constexpr int WNn = BN/WN;
    int wn_i = wid % WNn, wm_i = wid / WNn;
    constexpr int MF = WM/16, NF = WN/8;
    float acc[MF][NF][4];
    #pragma unroll
    for (int a = 0; a < MF; a++)
        #pragma unroll
        for (int b = 0; b < NF; b++)
            #pragma unroll
            for (int i = 0; i < 4; i++) acc[a][b][i] = 0.f;

    const int NIT = KD / BK;
    loadA(Asm[0], 0); loadB(Bsm[0], 0);
    asm volatile("cp.async.commit_group;");

    for (int it = 0; it < NIT; ++it) {
        if (it + 1 < NIT) {
            loadA(Asm[(it+1)&1], (it+1)*BK);
            loadB(Bsm[(it+1)&1], (it+1)*BK);
            asm volatile("cp.async.commit_group;");
            asm volatile("cp.async.wait_group 1;");
        } else {
            asm volatile("cp.async.wait_group 0;");
        }
        __syncthreads();
        const float* As = Asm[it & 1];
        const float* Bs = Bsm[it & 1];
        #pragma unroll
        for (int kf = 0; kf < BK/8; kf++) {
            unsigned af[MF][4]; unsigned bf[NF][2];
            #pragma unroll
            for (int mf = 0; mf < MF; mf++) {
                const float* Ab = As + (wm_i*WM + mf*16)*ASTR + kf*8;
                af[mf][0] = __float_as_uint(Ab[(g    )*ASTR + tq    ]);
                af[mf][1] = __float_as_uint(Ab[(g + 8)*ASTR + tq    ]);
                af[mf][2] = __float_as_uint(Ab[(g    )*ASTR + tq + 4]);
                af[mf][3] = __float_as_uint(Ab[(g + 8)*ASTR + tq + 4]);
            }
            #pragma unroll
            for (int nf = 0; nf < NF; nf++) {
                const float* Bb = Bs + (kf*8)*BSTR + wn_i*WN + nf*8 + g;
                bf[nf][0] = __float_as_uint(Bb[(tq    )*BSTR]);
                bf[nf][1] = __float_as_uint(Bb[(tq + 4)*BSTR]);
            }
            #pragma unroll
            for (int mf = 0; mf < MF; mf++)
                #pragma unroll
                for (int nf = 0; nf < NF; nf++)
                    mma_tf32(acc[mf][nf], af[mf][0], af[mf][1], af[mf][2], af[mf][3],
                             bf[nf][0], bf[nf][1]);
        }
        __syncthreads();
    }

    // epilogue
    #pragma unroll
    for (int mf = 0; mf < MF; mf++)
        #pragma unroll
        for (int nf = 0; nf < NF; nf++)
            #pragma unroll
            for (int i = 0; i < 4; i++) {
                int m = bm*BM + wm_i*WM + mf*16 + g + ((i & 2) ? 8 : 0);
                int n = bn*BN + wn_i*WN + nf*8 + tq*2 + (i & 1);
                float v = acc[mf][nf][i];
                if (MODE == MKV) {
                    v += bias[n]; v = rtf32(v);
                    int b = m >> 11, t = m & 2047, hh = n >> 6, d = n & 63;
                    out[(((long)(b*Hn + hh))*Tn + t)*HSn + d] = v;
                } else if (MODE == MQ) {
                    v = (v + bias[n]) * 0.03125f;  // fold C^-0.5 (exact pow2)
                    v = rtf32(v);
                    int b = m >> 10, s = m & 1023, hh = n >> 6, d = n & 63;
                    out[(((long)(b*Hn + hh))*CUTn + s)*HSn + d] = v;
                } else if (MODE == MPROJ) {
                    int b = m >> 10, s = m & 1023;
                    v += bias[n] + extra[((long)b*Tn + (Tn - CUTn) + s)*Cn + n];
                    out[(long)m*Cn + n] = v;
                } else if (MODE == MLIN1) {
                    v += bias[n];
                    v = 0.5f * v * (1.0f + erff(v * 0.70710678118654752f));
                    out[(long)m*(4*Cn) + n] = rtf32(v);
                } else { // MLIN2
                    v += bias[n] + extra[(long)m*Cn + n];
                    out[(long)m*Cn + n] = v;
                }
            }
}

// ---------------- host launcher ---------------------------------------------
extern "C" void kernel_launch(void* const* d_in, const int* in_sizes, int n_in,
                              void* d_out, int out_size)
{
    (void)in_sizes; (void)n_in; (void)out_size;
    const float* x      = (const float*)d_in[0];
    const float* ln1_w  = (const float*)d_in[1];
    const float* ln1_b  = (const float*)d_in[2];
    const float* Wq     = (const float*)d_in[3];
    const float* bq     = (const float*)d_in[4];
    const float* Wk     = (const float*)d_in[5];
    const float* bk     = (const float*)d_in[6];
    const float* Wv     = (const float*)d_in[7];
    const float* bv     = (const float*)d_in[8];
    const float* proj_w = (const float*)d_in[9];
    const float* proj_b = (const float*)d_in[10];
    const float* ln2_w  = (const float*)d_in[11];
    const float* ln2_b  = (const float*)d_in[12];
    const float* lin1_w = (const float*)d_in[13];
    const float* lin1_b = (const float*)d_in[14];
    const float* lin2_w = (const float*)d_in[15];
    const float* lin2_b = (const float*)d_in[16];
    float* out = (float*)d_out;

    float *p_h, *p_k, *p_v, *p_q, *p_o, *p_res, *p_h2, *p_ff;
    float *p_wq, *p_wk, *p_wv, *p_wp, *p_w1, *p_w2;
    cudaGetSymbolAddress((void**)&p_h,   g_h);
    cudaGetSymbolAddress((void**)&p_k,   g_k);
    cudaGetSymbolAddress((void**)&p_v,   g_v);
    cudaGetSymbolAddress((void**)&p_q,   g_q);
    cudaGetSymbolAddress((void**)&p_o,   g_o);
    cudaGetSymbolAddress((void**)&p_res, g_res);
    cudaGetSymbolAddress((void**)&p_h2,  g_h2);
    cudaGetSymbolAddress((void**)&p_ff,  g_ff);
    cudaGetSymbolAddress((void**)&p_wq,  g_wq);
    cudaGetSymbolAddress((void**)&p_wk,  g_wk);
    cudaGetSymbolAddress((void**)&p_wv,  g_wv);
    cudaGetSymbolAddress((void**)&p_wp,  g_wp);
    cudaGetSymbolAddress((void**)&p_w1,  g_w1);
    cudaGetSymbolAddress((void**)&p_w2,  g_w2);

    const int S_STD   = 2*(128*36 + 32*136)*4;   // 71680
    const int S_FLASH = (128*FQS + 2*64*FKS + 2*64*FVS + 128*FQS)*4;  // 141312
    cudaFuncSetAttribute((const void*)tc_gemm<MKV,  128,128,32,64,32>, cudaFuncAttributeMaxDynamicSharedMemorySize, S_STD);
    cudaFuncSetAttribute((const void*)tc_gemm<MQ,   128,128,32,64,32>, cudaFuncAttributeMaxDynamicSharedMemorySize, S_STD);
    cudaFuncSetAttribute((const void*)tc_gemm<MPROJ,128,128,32,64,32>, cudaFuncAttributeMaxDynamicSharedMemorySize, S_STD);
    cudaFuncSetAttribute((const void*)tc_gemm<MLIN1,128,128,32,64,32>, cudaFuncAttributeMaxDynamicSharedMemorySize, S_STD);
    cudaFuncSetAttribute((const void*)tc_gemm<MLIN2,128,128,32,64,32>, cudaFuncAttributeMaxDynamicSharedMemorySize, S_STD);
    cudaFuncSetAttribute((const void*)flash_kernel, cudaFuncAttributeMaxDynamicSharedMemorySize, S_FLASH);

    // 0) one merged tf32 rounding prepass (launch #1)
    RoundArgs ra;
    const int WSZ4 = Hn*Cn*HSn/4;      // 262144
    ra.s[0] = (const float4*)Wq;     ra.d[0] = (float4*)p_wq;
    ra.s[1] = (const float4*)Wk;     ra.d[1] = (float4*)p_wk;
    ra.s[2] = (const float4*)Wv;     ra.d[2] = (float4*)p_wv;
    ra.s[3] = (const float4*)proj_w; ra.d[3] = (float4*)p_wp;
    ra.s[4] = (const float4*)lin1_w; ra.d[4] = (float4*)p_w1;
    ra.s[5] = (const float4*)lin2_w; ra.d[5] = (float4*)p_w2;
    ra.end[0] = WSZ4;               ra.end[1] = 2*WSZ4;
    ra.end[2] = 3*WSZ4;             ra.end[3] = 3*WSZ4 + Cn*Cn/4;
    ra.end[4] = ra.end[3] + Cn*4*Cn/4;
    ra.end[5] = ra.end[4] + 4*Cn*Cn/4;
    round_all<<<(ra.end[5] + 255)/256, 256>>>(ra);

    // 1) LN1 (launch #2)
    ln_kernel<<<Bn*Tn, 256>>>(x, ln1_w, ln1_b, p_h);

    // 2) K, V projections (launches #3, #4)
    tc_gemm<MKV,128,128,32,64,32><<<dim3(8,64), 256, S_STD>>>(p_h, p_wk, bk, nullptr, p_k);
    tc_gemm<MKV,128,128,32,64,32><<<dim3(8,64), 256, S_STD>>>(p_h, p_wv, bv, nullptr, p_v);

    // 3) Q projection (launch #5)
    tc_gemm<MQ,128,128,32,64,32><<<dim3(8,32), 256, S_STD>>>(p_h, p_wq, bq, nullptr, p_q);

    // 4) fused flash attention (launch #6 — ncu profile target)
    flash_kernel<<<dim3(8,64), 256, S_FLASH>>>(p_q, p_k, p_v, p_o);

    // 5) res = x_tail + o @ proj_w + proj_b
    tc_gemm<MPROJ,128,128,32,64,32><<<dim3(8,32), 256, S_STD>>>(p_o, p_wp, proj_b, x, p_res);

    // 6) LN2
    ln_kernel<<<Bn*CUTn, 256>>>(p_res, ln2_w, ln2_b, p_h2);

    // 7) ff = gelu(h2 @ lin1_w + lin1_b)
    tc_gemm<MLIN1,128,128,32,64,32><<<dim3(32,32), 256, S_STD>>>(p_h2, p_w1, lin1_b, nullptr, p_ff);

    // 8) out = res + ff @ lin2_w + lin2_b
    tc_gemm<MLIN2,128,128,32,64,32><<<dim3(8,32), 256, S_STD>>>(p_ff, p_w2, lin2_b, p_res, out);
}

// round 4
// speedup vs baseline: 3.9300x; 1.1482x over previous
#include <cuda_runtime.h>
#include <math.h>

// Shapes (fixed by problem)
#define Bn   4
#define Tn   2048
#define Cn   1024
#define Hn   16
#define HSn  64
#define CUTn 1024

// ---------------- scratch ---------------------------------------------------
__device__ float g_h   [Bn*Tn*Cn];
__device__ float g_k   [Bn*Hn*Tn*HSn];
__device__ float g_v   [Bn*Hn*Tn*HSn];
__device__ float g_q   [Bn*Hn*CUTn*HSn];
__device__ float g_o   [Bn*CUTn*Cn];
__device__ float g_res [Bn*CUTn*Cn];
__device__ float g_h2  [Bn*CUTn*Cn];
__device__ float g_ff  [Bn*CUTn*4*Cn];
// tf32-rounded weight copies
__device__ float g_wq  [Hn*Cn*HSn];
__device__ float g_wk  [Hn*Cn*HSn];
__device__ float g_wv  [Hn*Cn*HSn];
__device__ float g_wp  [Cn*Cn];
__device__ float g_w1  [Cn*4*Cn];
__device__ float g_w2  [4*Cn*Cn];

__device__ __forceinline__ float rtf32(float x) {
    unsigned u;
    asm("cvt.rna.tf32.f32 %0, %1;" : "=r"(u) : "f"(x));
    return __uint_as_float(u);
}
__device__ __forceinline__ void cpasync16(float* d, const float* s) {
    unsigned u = (unsigned)__cvta_generic_to_shared(d);
    asm volatile("cp.async.cg.shared.global [%0], [%1], 16;" :: "r"(u), "l"(s));
}
__device__ __forceinline__ void mma_tf32(float* c, unsigned a0, unsigned a1,
                                         unsigned a2, unsigned a3,
                                         unsigned b0, unsigned b1) {
    asm volatile(
        "mma.sync.aligned.m16n8k8.row.col.f32.tf32.tf32.f32 "
        "{%0,%1,%2,%3},{%4,%5,%6,%7},{%8,%9},{%0,%1,%2,%3};"
        : "+f"(c[0]), "+f"(c[1]), "+f"(c[2]), "+f"(c[3])
        : "r"(a0), "r"(a1), "r"(a2), "r"(a3), "r"(b0), "r"(b1));
}
// ldmatrix.x4: loads the 16x8 tf32 A-fragment (4 LDSM matrices of 8 rows x 16B).
// Caller passes the per-lane row/col-offset pointer.
__device__ __forceinline__ void ldsm4(unsigned* r, const float* p) {
    unsigned a = (unsigned)__cvta_generic_to_shared(p);
    asm volatile("ldmatrix.sync.aligned.m8n8.x4.shared.b16 {%0,%1,%2,%3}, [%4];"
                 : "=r"(r[0]), "=r"(r[1]), "=r"(r[2]), "=r"(r[3]) : "r"(a));
}

// ---------------- merged weight tf32 rounding prepass -----------------------
struct RoundArgs {
    const float4* s[6];
    float4*       d[6];
    int           end[6];
};
__global__ void __launch_bounds__(256) round_all(RoundArgs a)
{
    int i = blockIdx.x * 256 + threadIdx.x;
    if (i >= a.end[5]) return;
    int r = 0, base = 0;
    #pragma unroll
    for (int j = 0; j < 5; j++)
        if (i >= a.end[j]) { r = j + 1; base = a.end[j]; }
    float4 v = a.s[r][i - base];
    v.x = rtf32(v.x); v.y = rtf32(v.y); v.z = rtf32(v.z); v.w = rtf32(v.w);
    a.d[r][i - base] = v;
}

// ---------------- LayerNorm (tf32-rounded output) ---------------------------
__global__ void __launch_bounds__(256) ln_kernel(const float* __restrict__ x,
                                                 const float* __restrict__ w,
                                                 const float* __restrict__ b,
                                                 float* __restrict__ out)
{
    long row = blockIdx.x;
    int t = threadIdx.x;
    const float4* xr = (const float4*)(x + row * Cn);
    float4 v = xr[t];
    float s  = v.x + v.y + v.z + v.w;
    float s2 = v.x*v.x + v.y*v.y + v.z*v.z + v.w*v.w;
    #pragma unroll
    for (int o = 16; o; o >>= 1) {
        s  += __shfl_xor_sync(0xffffffffu, s,  o);
        s2 += __shfl_xor_sync(0xffffffffu, s2, o);
    }
    __shared__ float rs[8], rs2[8];
    if ((t & 31) == 0) { rs[t >> 5] = s; rs2[t >> 5] = s2; }
    __syncthreads();
    float a = 0.f, c = 0.f;
    #pragma unroll
    for (int i = 0; i < 8; i++) { a += rs[i]; c += rs2[i]; }
    float mean = a * (1.0f / Cn);
    float var  = c * (1.0f / Cn) - mean * mean;
    float inv  = rsqrtf(var + 1e-5f);
    float4 wv = ((const float4*)w)[t];
    float4 bv = ((const float4*)b)[t];
    float4 o4;
    o4.x = rtf32((v.x - mean) * inv * wv.x + bv.x);
    o4.y = rtf32((v.y - mean) * inv * wv.y + bv.y);
    o4.z = rtf32((v.z - mean) * inv * wv.z + bv.z);
    o4.w = rtf32((v.w - mean) * inv * wv.w + bv.w);
    ((float4*)(out + row * Cn))[t] = o4;
}

// ---------------- fused flash attention -------------------------------------
#define FQS 68
#define FKS 68
#define FVS 72

__global__ void __launch_bounds__(256) flash_kernel(
    const float* __restrict__ Q, const float* __restrict__ K,
    const float* __restrict__ V, float* __restrict__ O)
{
    int bm = blockIdx.x, z = blockIdx.y;
    const float* Qz = Q + (long)z*(CUTn*HSn) + (long)bm*128*HSn;
    const float* Kz = K + (long)z*(Tn*HSn);
    const float* Vz = V + (long)z*(Tn*HSn);

    extern __shared__ float sm[];
    float* Qs  = sm;
    float* Ksm = Qs  + 128*FQS;
    float* Vsm = Ksm + 2*64*FKS;
    float* Ps  = Vsm + 2*64*FVS;

    int tid = threadIdx.x, lane = tid & 31, wid = tid >> 5;
    int g = lane >> 2, tq = lane & 3;
    // ldmatrix per-lane offsets
    int arow = (lane & 7) + ((lane & 8) ? 8 : 0);
    int acol = (lane & 16) ? 4 : 0;

    #pragma unroll
    for (int i = 0; i < 8; i++) {
        int c = i*256 + tid; int r = c >> 4, cq = (c & 15) * 4;
        cpasync16(Qs + r*FQS + cq, Qz + r*64 + cq);
    }
    #pragma unroll
    for (int i = 0; i < 4; i++) {
        int c = i*256 + tid; int r = c >> 4, cq = (c & 15) * 4;
        cpasync16(Ksm + r*FKS + cq, Kz + r*64 + cq);
        cpasync16(Vsm + r*FVS + cq, Vz + r*64 + cq);
    }
    asm volatile("cp.async.commit_group;");

    float m0 = -1e30f, m1 = -1e30f, l0 = 0.f, l1 = 0.f;
    float oacc[8][4];
    #pragma unroll
    for (int j = 0; j < 8; j++) { oacc[j][0]=0.f; oacc[j][1]=0.f; oacc[j][2]=0.f; oacc[j][3]=0.f; }

    const int ktmax  = min(31, 17 + 2*bm);
    const int ktfull = 15 + 2*bm;
    const int sg0    = bm*128 + wid*16 + g;

    for (int kt = 0; kt <= ktmax; kt++) {
        int buf = kt & 1;
        if (kt < ktmax) {
            const float* Kp = Kz + (long)(kt+1)*64*64;
            const float* Vp = Vz + (long)(kt+1)*64*64;
            int b2 = buf ^ 1;
            #pragma unroll
            for (int i = 0; i < 4; i++) {
                int c = i*256 + tid; int r = c >> 4, cq = (c & 15) * 4;
                cpasync16(Ksm + b2*64*FKS + r*FKS + cq, Kp + r*64 + cq);
                cpasync16(Vsm + b2*64*FVS + r*FVS + cq, Vp + r*64 + cq);
            }
            asm volatile("cp.async.commit_group;");
            asm volatile("cp.async.wait_group 1;");
        } else {
            asm volatile("cp.async.wait_group 0;");
        }
        __syncthreads();

        // S = Q.K^T
        float sacc[8][4];
        #pragma unroll
        for (int j = 0; j < 8; j++) { sacc[j][0]=0.f; sacc[j][1]=0.f; sacc[j][2]=0.f; sacc[j][3]=0.f; }
        const float* Kb = Ksm + buf*64*FKS;
        #pragma unroll
        for (int kf = 0; kf < 8; kf++) {
            unsigned af[4];
            ldsm4(af, Qs + (wid*16 + arow)*FQS + kf*8 + acol);
            #pragma unroll
            for (int nf = 0; nf < 8; nf++) {
                const float* Bb = Kb + (nf*8 + g)*FKS + kf*8;
                mma_tf32(sacc[nf], af[0], af[1], af[2], af[3],
                         __float_as_uint(Bb[tq]), __float_as_uint(Bb[tq + 4]));
            }
        }
        if (kt > ktfull) {
            #pragma unroll
            for (int nf = 0; nf < 8; nf++)
                #pragma unroll
                for (int i = 0; i < 4; i++) {
                    int jg = kt*64 + nf*8 + tq*2 + (i & 1);
                    int sg = sg0 + ((i & 2) ? 8 : 0);
                    if (jg > 1024 + sg) sacc[nf][i] = -1e30f;
                }
        }
        // online softmax
        float mx0 = -1e30f, mx1 = -1e30f;
        #pragma unroll
        for (int nf = 0; nf < 8; nf++) {
            mx0 = fmaxf(mx0, fmaxf(sacc[nf][0], sacc[nf][1]));
            mx1 = fmaxf(mx1, fmaxf(sacc[nf][2], sacc[nf][3]));
        }
        mx0 = fmaxf(mx0, __shfl_xor_sync(0xffffffffu, mx0, 1));
        mx0 = fmaxf(mx0, __shfl_xor_sync(0xffffffffu, mx0, 2));
        mx1 = fmaxf(mx1, __shfl_xor_sync(0xffffffffu, mx1, 1));
        mx1 = fmaxf(mx1, __shfl_xor_sync(0xffffffffu, mx1, 2));
        float mn0 = fmaxf(m0, mx0), mn1 = fmaxf(m1, mx1);
        float f0 = __expf(m0 - mn0), f1 = __expf(m1 - mn1);
        float s0 = 0.f, s1 = 0.f;
        float* Pw0 = Ps + (wid*16 + g    )*FQS + tq*2;
        float* Pw1 = Ps + (wid*16 + g + 8)*FQS + tq*2;
        #pragma unroll
        for (int nf = 0; nf < 8; nf++) {
            float p0 = __expf(sacc[nf][0] - mn0), p1 = __expf(sacc[nf][1] - mn0);
            float p2 = __expf(sacc[nf][2] - mn1), p3 = __expf(sacc[nf][3] - mn1);
            s0 += p0 + p1; s1 += p2 + p3;
            *(float2*)(Pw0 + nf*8) = make_float2(p0, p1);
            *(float2*)(Pw1 + nf*8) = make_float2(p2, p3);
        }
        s0 += __shfl_xor_sync(0xffffffffu, s0, 1); s0 += __shfl_xor_sync(0xffffffffu, s0, 2);
        s1 += __shfl_xor_sync(0xffffffffu, s1, 1); s1 += __shfl_xor_sync(0xffffffffu, s1, 2);
        l0 = l0*f0 + s0; l1 = l1*f1 + s1; m0 = mn0; m1 = mn1;
        #pragma unroll
        for (int j = 0; j < 8; j++) {
            oacc[j][0] *= f0; oacc[j][1] *= f0; oacc[j][2] *= f1; oacc[j][3] *= f1;
        }
        __syncwarp();

        // O += P.V
        const float* Vb = Vsm + buf*64*FVS;
        #pragma unroll
        for (int kf = 0; kf < 8; kf++) {
            unsigned af[4];
            ldsm4(af, Ps + (wid*16 + arow)*FQS + kf*8 + acol);
            #pragma unroll
            for (int nf = 0; nf < 8; nf++) {
                const float* Bb = Vb + (kf*8)*FVS + nf*8 + g;
                mma_tf32(oacc[nf], af[0], af[1], af[2], af[3],
                         __float_as_uint(Bb[ tq     *FVS]),
                         __float_as_uint(Bb[(tq + 4)*FVS]));
            }
        }
        __syncthreads();
    }

    int b = z >> 4, hh = z & 15;
    float il0 = 1.f / l0, il1 = 1.f / l1;
    #pragma unroll
    for (int nf = 0; nf < 8; nf++)
        #pragma unroll
        for (int i = 0; i < 4; i++) {
            int row = wid*16 + g + ((i & 2) ? 8 : 0);
            int s = bm*128 + row;
            int d = nf*8 + tq*2 + (i & 1);
            O[((long)b*CUTn + s)*Cn + hh*64 + d] = rtf32(oacc[nf][i] * ((i & 2) ? il1 : il0));
        }
}

// ---------------- tensor-core tf32 GEMM (3-stage, ldmatrix) -----------------
#define MKV   0
#define MQ    1
#define MPROJ 4
#define MLIN1 5
#define MLIN2 6

template<int MODE, int BM, int BN, int BK, int WM, int WN>
__global__ void __launch_bounds__(256) tc_gemm(
    const float* __restrict__ A, const float* __restrict__ Bm,
    const float* __restrict__ bias, const float* __restrict__ extra,
    float* __restrict__ out)
{
    constexpr int KD  = (MODE==MLIN2) ? 4096 : 1024;
    constexpr int LDA = (MODE==MLIN2) ? 4096 : 1024;
    constexpr int LDB = (MODE==MLIN1) ? 4096 : 1024;
    constexpr int ASTR = BK + 4;
    constexpr int BSTR = BN + 8;
    constexpr int ASZ  = BM * ASTR;
    constexpr int BSZ  = BK * BSTR;

    extern __shared__ float smp[];
    float* Asm[3] = { smp, smp + (ASZ+BSZ), smp + 2*(ASZ+BSZ) };
    float* Bsm[3] = { smp + ASZ, smp + (ASZ+BSZ) + ASZ, smp + 2*(ASZ+BSZ) + ASZ };

    int bn = blockIdx.x, bm = blockIdx.y;
    int tid = threadIdx.x;

    auto loadA = [&](float* As, int k0) {
        constexpr int NCH = BM*BK/4/256;
        #pragma unroll
        for (int i = 0; i < NCH; i++) {
            int c = i*256 + tid;
            int m = c >> 3;
            int kq = (c & 7) * 4;
            long src;
            if (MODE == MQ) {
                int r = bm*BM + m;
                src = ((long)(r >> 10)*Tn + (Tn - CUTn) + (r & 1023))*(long)Cn + k0 + kq;
            } else {
                src = (long)(bm*BM + m)*LDA + k0 + kq;
            }
            cpasync16(As + m*ASTR + kq, A + src);
        }
    };
    auto loadB = [&](float* Bs, int k0) {
        constexpr int CPR = BN/4;
        constexpr int NCH = BK*BN/4/256;
        #pragma unroll
        for (int i = 0; i < NCH; i++) {
            int c = i*256 + tid; int k = c / CPR; int nq = (c % CPR)*4;
            long src;
            if (MODE == MKV || MODE == MQ) {
                int n = bn*BN + nq;
                src = (long)(n >> 6)*(Cn*HSn) + (long)(k0 + k)*HSn + (n & 63);
            } else {
                src = (long)(k0 + k)*LDB + bn*BN + nq;
            }
            cpasync16(Bs + k*BSTR + nq, Bm + src);
        }
    };

    int lane = tid & 31, g = lane >> 2, tq = lane & 3;
    int wid = tid >> 5;
    int arow = (lane & 7) + ((lane & 8) ? 8 : 0);
    int acol = (lane & 16) ? 4 : 0;
    constexpr int WNn = BN/WN;
    int wn_i = wid % WNn, wm_i = wid / WNn;
    constexpr int MF = WM/16, NF = WN/8;
    float acc[MF][NF][4];
    #pragma unroll
    for (int a = 0; a < MF; a++)
        #pragma unroll
        for (int b = 0; b < NF; b++)
            #pragma unroll
            for (int i = 0; i < 4; i++) acc[a][b][i] = 0.f;

    const int NIT = KD / BK;
    loadA(Asm[0], 0);  loadB(Bsm[0], 0);
    asm volatile("cp.async.commit_group;");
    loadA(Asm[1], BK); loadB(Bsm[1], BK);
    asm volatile("cp.async.commit_group;");
    asm volatile("cp.async.wait_group 1;");
    __syncthreads();

    for (int it = 0; it < NIT; ++it) {
        int cur = it % 3;
        const float* As = Asm[cur];
        const float* Bs = Bsm[cur];
        #pragma unroll
        for (int kf = 0; kf < BK/8; kf++) {
            unsigned af[MF][4]; unsigned bf[NF][2];
            #pragma unroll
            for (int mf = 0; mf < MF; mf++)
                ldsm4(af[mf], As + (wm_i*WM + mf*16 + arow)*ASTR + kf*8 + acol);
            #pragma unroll
            for (int nf = 0; nf < NF; nf++) {
                const float* Bb = Bs + (kf*8)*BSTR + wn_i*WN + nf*8 + g;
                bf[nf][0] = __float_as_uint(Bb[(tq    )*BSTR]);
                bf[nf][1] = __float_as_uint(Bb[(tq + 4)*BSTR]);
            }
            #pragma unroll
            for (int mf = 0; mf < MF; mf++)
                #pragma unroll
                for (int nf = 0; nf < NF; nf++)
                    mma_tf32(acc[mf][nf], af[mf][0], af[mf][1], af[mf][2], af[mf][3],
                             bf[nf][0], bf[nf][1]);
        }
        if (it + 2 < NIT) {
            int nxt = (it + 2) % 3;
            loadA(Asm[nxt], (it+2)*BK);
            loadB(Bsm[nxt], (it+2)*BK);
            asm volatile("cp.async.commit_group;");
            asm volatile("cp.async.wait_group 1;");
        } else if (it + 1 < NIT) {
            asm volatile("cp.async.wait_group 0;");
        }
        if (it + 1 < NIT) __syncthreads();
    }

    // epilogue
    #pragma unroll
    for (int mf = 0; mf < MF; mf++)
        #pragma unroll
        for (int nf = 0; nf < NF; nf++)
            #pragma unroll
            for (int i = 0; i < 4; i++) {
                int m = bm*BM + wm_i*WM + mf*16 + g + ((i & 2) ? 8 : 0);
                int n = bn*BN + wn_i*WN + nf*8 + tq*2 + (i & 1);
                float v = acc[mf][nf][i];
                if (MODE == MKV) {
                    v += bias[n]; v = rtf32(v);
                    int b = m >> 11, t = m & 2047, hh = n >> 6, d = n & 63;
                    out[(((long)(b*Hn + hh))*Tn + t)*HSn + d] = v;
                } else if (MODE == MQ) {
                    v = (v + bias[n]) * 0.03125f;
                    v = rtf32(v);
                    int b = m >> 10, s = m & 1023, hh = n >> 6, d = n & 63;
                    out[(((long)(b*Hn + hh))*CUTn + s)*HSn + d] = v;
                } else if (MODE == MPROJ) {
                    int b = m >> 10, s = m & 1023;
                    v += bias[n] + extra[((long)b*Tn + (Tn - CUTn) + s)*Cn + n];
                    out[(long)m*Cn + n] = v;
                } else if (MODE == MLIN1) {
                    v += bias[n];
                    v = 0.5f * v * (1.0f + erff(v * 0.70710678118654752f));
                    out[(long)m*(4*Cn) + n] = rtf32(v);
                } else { // MLIN2
                    v += bias[n] + extra[(long)m*Cn + n];
                    out[(long)m*Cn + n] = v;
                }
            }
}

// ---------------- host launcher ---------------------------------------------
extern "C" void kernel_launch(void* const* d_in, const int* in_sizes, int n_in,
                              void* d_out, int out_size)
{
    (void)in_sizes; (void)n_in; (void)out_size;
    const float* x      = (const float*)d_in[0];
    const float* ln1_w  = (const float*)d_in[1];
    const float* ln1_b  = (const float*)d_in[2];
    const float* Wq     = (const float*)d_in[3];
    const float* bq     = (const float*)d_in[4];
    const float* Wk     = (const float*)d_in[5];
    const float* bk     = (const float*)d_in[6];
    const float* Wv     = (const float*)d_in[7];
    const float* bv     = (const float*)d_in[8];
    const float* proj_w = (const float*)d_in[9];
    const float* proj_b = (const float*)d_in[10];
    const float* ln2_w  = (const float*)d_in[11];
    const float* ln2_b  = (const float*)d_in[12];
    const float* lin1_w = (const float*)d_in[13];
    const float* lin1_b = (const float*)d_in[14];
    const float* lin2_w = (const float*)d_in[15];
    const float* lin2_b = (const float*)d_in[16];
    float* out = (float*)d_out;

    float *p_h, *p_k, *p_v, *p_q, *p_o, *p_res, *p_h2, *p_ff;
    float *p_wq, *p_wk, *p_wv, *p_wp, *p_w1, *p_w2;
    cudaGetSymbolAddress((void**)&p_h,   g_h);
    cudaGetSymbolAddress((void**)&p_k,   g_k);
    cudaGetSymbolAddress((void**)&p_v,   g_v);
    cudaGetSymbolAddress((void**)&p_q,   g_q);
    cudaGetSymbolAddress((void**)&p_o,   g_o);
    cudaGetSymbolAddress((void**)&p_res, g_res);
    cudaGetSymbolAddress((void**)&p_h2,  g_h2);
    cudaGetSymbolAddress((void**)&p_ff,  g_ff);
    cudaGetSymbolAddress((void**)&p_wq,  g_wq);
    cudaGetSymbolAddress((void**)&p_wk,  g_wk);
    cudaGetSymbolAddress((void**)&p_wv,  g_wv);
    cudaGetSymbolAddress((void**)&p_wp,  g_wp);
    cudaGetSymbolAddress((void**)&p_w1,  g_w1);
    cudaGetSymbolAddress((void**)&p_w2,  g_w2);

    const int S_STD   = 3*(128*36 + 32*136)*4;   // 107520 (3-stage)
    const int S_FLASH = (128*FQS + 2*64*FKS + 2*64*FVS + 128*FQS)*4;
    cudaFuncSetAttribute((const void*)tc_gemm<MKV,  128,128,32,64,32>, cudaFuncAttributeMaxDynamicSharedMemorySize, S_STD);
    cudaFuncSetAttribute((const void*)tc_gemm<MQ,   128,128,32,64,32>, cudaFuncAttributeMaxDynamicSharedMemorySize, S_STD);
    cudaFuncSetAttribute((const void*)tc_gemm<MPROJ,128,128,32,64,32>, cudaFuncAttributeMaxDynamicSharedMemorySize, S_STD);
    cudaFuncSetAttribute((const void*)tc_gemm<MLIN1,128,128,32,64,32>, cudaFuncAttributeMaxDynamicSharedMemorySize, S_STD);
    cudaFuncSetAttribute((const void*)tc_gemm<MLIN2,128,128,32,64,32>, cudaFuncAttributeMaxDynamicSharedMemorySize, S_STD);
    cudaFuncSetAttribute((const void*)flash_kernel, cudaFuncAttributeMaxDynamicSharedMemorySize, S_FLASH);

    RoundArgs ra;
    const int WSZ4 = Hn*Cn*HSn/4;
    ra.s[0] = (const float4*)Wq;     ra.d[0] = (float4*)p_wq;
    ra.s[1] = (const float4*)Wk;     ra.d[1] = (float4*)p_wk;
    ra.s[2] = (const float4*)Wv;     ra.d[2] = (float4*)p_wv;
    ra.s[3] = (const float4*)proj_w; ra.d[3] = (float4*)p_wp;
    ra.s[4] = (const float4*)lin1_w; ra.d[4] = (float4*)p_w1;
    ra.s[5] = (const float4*)lin2_w; ra.d[5] = (float4*)p_w2;
    ra.end[0] = WSZ4;               ra.end[1] = 2*WSZ4;
    ra.end[2] = 3*WSZ4;             ra.end[3] = 3*WSZ4 + Cn*Cn/4;
    ra.end[4] = ra.end[3] + Cn*4*Cn/4;
    ra.end[5] = ra.end[4] + 4*Cn*Cn/4;
    round_all<<<(ra.end[5] + 255)/256, 256>>>(ra);

    ln_kernel<<<Bn*Tn, 256>>>(x, ln1_w, ln1_b, p_h);

    tc_gemm<MKV,128,128,32,64,32><<<dim3(8,64), 256, S_STD>>>(p_h, p_wk, bk, nullptr, p_k);
    tc_gemm<MKV,128,128,32,64,32><<<dim3(8,64), 256, S_STD>>>(p_h, p_wv, bv, nullptr, p_v);

    tc_gemm<MQ,128,128,32,64,32><<<dim3(8,32), 256, S_STD>>>(p_h, p_wq, bq, nullptr, p_q);

    flash_kernel<<<dim3(8,64), 256, S_FLASH>>>(p_q, p_k, p_v, p_o);

    tc_gemm<MPROJ,128,128,32,64,32><<<dim3(8,32), 256, S_STD>>>(p_o, p_wp, proj_b, x, p_res);

    ln_kernel<<<Bn*CUTn, 256>>>(p_res, ln2_w, ln2_b, p_h2);

    tc_gemm<MLIN1,128,128,32,64,32><<<dim3(32,32), 256, S_STD>>>(p_h2, p_w1, lin1_b, nullptr, p_ff);

    tc_gemm<MLIN2,128,128,32,64,32><<<dim3(8,32), 256, S_STD>>>(p_ff, p_w2, lin2_b, p_res, out);
}